// round 2
// baseline (speedup 1.0000x reference)
#include <cuda_runtime.h>
#include <cuda_fp16.h>
#include <mma.h>
#include <math.h>

using namespace nvcuda;

#define VOCAB 5000
#define EMB   512
#define HID   1024
#define GATES 4096
#define BATCH 32
#define SEQ   512
#define MROWS (BATCH*SEQ)   /* 16384 */
#define VPAD  5056          /* 79 * 64 */

// ---------------------------------------------------------------------------
// Static device scratch (no allocations allowed in kernel_launch)
// ---------------------------------------------------------------------------
__device__ __half g_emb_hi[VOCAB*EMB];
__device__ __half g_emb_lo[VOCAB*EMB];
__device__ __half g_Wih_hi[GATES*EMB];
__device__ __half g_Wih_lo[GATES*EMB];
__device__ __half g_Whh_hi[GATES*HID];
__device__ __half g_Whh_lo[GATES*HID];
__device__ __half g_Wfc_hi[VPAD*HID];
__device__ __half g_Wfc_lo[VPAD*HID];
__device__ float  g_xg[(size_t)MROWS*GATES];     // 268 MB: precomputed x@W_ih^T
__device__ __half g_hs_hi[MROWS*HID];            // all h_t (hi part)
__device__ __half g_hs_lo[MROWS*HID];            // all h_t (lo part)
__device__ __half g_h_hi[2][BATCH*HID];          // double-buffered h
__device__ __half g_h_lo[2][BATCH*HID];
__device__ float  g_c[BATCH*HID];

// ---------------------------------------------------------------------------
// Prep: split fp32 weights into fp16 hi/lo pairs (error-compensated MMA)
// ---------------------------------------------------------------------------
__device__ __forceinline__ void split1(float f, __half* hi, __half* lo, int i) {
    __half h = __float2half_rn(f);
    hi[i] = h;
    lo[i] = __float2half_rn(f - __half2float(h));
}

__global__ void prep_emb(const float* __restrict__ src) {
    for (int i = blockIdx.x*blockDim.x + threadIdx.x; i < VOCAB*EMB; i += gridDim.x*blockDim.x)
        split1(src[i], g_emb_hi, g_emb_lo, i);
}
__global__ void prep_wih(const float* __restrict__ src) {
    for (int i = blockIdx.x*blockDim.x + threadIdx.x; i < GATES*EMB; i += gridDim.x*blockDim.x)
        split1(src[i], g_Wih_hi, g_Wih_lo, i);
}
__global__ void prep_whh(const float* __restrict__ src) {
    for (int i = blockIdx.x*blockDim.x + threadIdx.x; i < GATES*HID; i += gridDim.x*blockDim.x)
        split1(src[i], g_Whh_hi, g_Whh_lo, i);
}
__global__ void prep_wfc(const float* __restrict__ src) {
    for (int i = blockIdx.x*blockDim.x + threadIdx.x; i < VPAD*HID; i += gridDim.x*blockDim.x) {
        float f = (i < VOCAB*HID) ? src[i] : 0.0f;   // rows padded at the end
        split1(f, g_Wfc_hi, g_Wfc_lo, i);
    }
}
__global__ void init_state() {
    int i = blockIdx.x*blockDim.x + threadIdx.x;
    if (i < BATCH*HID) {
        g_c[i] = 0.0f;
        g_h_hi[0][i] = __float2half_rn(0.0f);
        g_h_lo[0][i] = __float2half_rn(0.0f);
    }
}

// ---------------------------------------------------------------------------
// Kernel 1: xg[m, 0:4096] = emb[x[m]] @ W_ih^T      (M=16384, N=4096, K=512)
// 64x64 CTA tile, 4 warps (2x2), each warp 32x32 (2x2 wmma m16n16k16 tiles),
// 3-pass hi/lo compensated fp16 MMA.
// ---------------------------------------------------------------------------
__global__ __launch_bounds__(128) void embed_gemm(const int* __restrict__ x) {
    __shared__ __align__(32) __half As_hi[64*24], As_lo[64*24];
    __shared__ __align__(32) __half Bs_hi[64*24], Bs_lo[64*24];
    __shared__ int rowidx[64];

    const int n0 = blockIdx.x * 64;
    const int m0 = blockIdx.y * 64;
    const int tid = threadIdx.x;
    const int warp = tid >> 5;
    const int wm = warp >> 1, wn = warp & 1;

    if (tid < 64) rowidx[tid] = x[m0 + tid];
    __syncthreads();

    wmma::fragment<wmma::accumulator, 16, 16, 16, float> acc[2][2];
    #pragma unroll
    for (int i = 0; i < 2; i++)
        #pragma unroll
        for (int j = 0; j < 2; j++)
            wmma::fill_fragment(acc[i][j], 0.0f);

    const int lrow = tid >> 1;
    const int lcol = (tid & 1) * 8;

    for (int k0 = 0; k0 < EMB; k0 += 16) {
        const int r = rowidx[lrow];
        *(int4*)(As_hi + lrow*24 + lcol) = *(const int4*)(g_emb_hi + r*EMB + k0 + lcol);
        *(int4*)(As_lo + lrow*24 + lcol) = *(const int4*)(g_emb_lo + r*EMB + k0 + lcol);
        const int n = n0 + lrow;
        *(int4*)(Bs_hi + lrow*24 + lcol) = *(const int4*)(g_Wih_hi + n*EMB + k0 + lcol);
        *(int4*)(Bs_lo + lrow*24 + lcol) = *(const int4*)(g_Wih_lo + n*EMB + k0 + lcol);
        __syncthreads();

        wmma::fragment<wmma::matrix_a, 16, 16, 16, __half, wmma::row_major> a_hi[2], a_lo[2];
        wmma::fragment<wmma::matrix_b, 16, 16, 16, __half, wmma::col_major> b_hi[2], b_lo[2];
        #pragma unroll
        for (int i = 0; i < 2; i++) {
            wmma::load_matrix_sync(a_hi[i], As_hi + (wm*32 + i*16)*24, 24);
            wmma::load_matrix_sync(a_lo[i], As_lo + (wm*32 + i*16)*24, 24);
        }
        #pragma unroll
        for (int j = 0; j < 2; j++) {
            wmma::load_matrix_sync(b_hi[j], Bs_hi + (wn*32 + j*16)*24, 24);
            wmma::load_matrix_sync(b_lo[j], Bs_lo + (wn*32 + j*16)*24, 24);
        }
        #pragma unroll
        for (int i = 0; i < 2; i++)
            #pragma unroll
            for (int j = 0; j < 2; j++) {
                wmma::mma_sync(acc[i][j], a_hi[i], b_hi[j], acc[i][j]);
                wmma::mma_sync(acc[i][j], a_hi[i], b_lo[j], acc[i][j]);
                wmma::mma_sync(acc[i][j], a_lo[i], b_hi[j], acc[i][j]);
            }
        __syncthreads();
    }

    #pragma unroll
    for (int i = 0; i < 2; i++)
        #pragma unroll
        for (int j = 0; j < 2; j++)
            wmma::store_matrix_sync(
                g_xg + (size_t)(m0 + wm*32 + i*16)*GATES + n0 + wn*32 + j*16,
                acc[i][j], GATES, wmma::mem_row_major);
}

// ---------------------------------------------------------------------------
// Kernel 2 (x512): one LSTM timestep.
// 64 CTAs; CTA owns a 16-wide j-slice; warp w computes gate w for that slice.
// gates[32, {i,f,g,o}@j..j+15] = h @ W_hh^T  (K=1024, 3-pass hi/lo),
// then fused cell update + h split + hs store. h double-buffered on s&1.
// ---------------------------------------------------------------------------
__global__ __launch_bounds__(128) void lstm_step(int s,
                                                 const float* __restrict__ b_ih,
                                                 const float* __restrict__ b_hh) {
    __shared__ __align__(32) __half As_hi[32*24], As_lo[32*24];
    __shared__ __align__(32) __half Bs_hi[64*24], Bs_lo[64*24];
    __shared__ __align__(32) float  gsm[32*68];

    const int j0 = blockIdx.x * 16;
    const int tid = threadIdx.x;
    const int warp = tid >> 5;

    const __half* __restrict__ hc_hi = g_h_hi[s & 1];
    const __half* __restrict__ hc_lo = g_h_lo[s & 1];
    __half* __restrict__ hn_hi = g_h_hi[(s & 1) ^ 1];
    __half* __restrict__ hn_lo = g_h_lo[(s & 1) ^ 1];

    wmma::fragment<wmma::accumulator, 16, 16, 16, float> acc[2];
    wmma::fill_fragment(acc[0], 0.0f);
    wmma::fill_fragment(acc[1], 0.0f);

    const int arow = tid >> 2, acol = (tid & 3) * 4;   // A: 32x16, 8B each
    const int brow = tid >> 1, bcol = (tid & 1) * 8;   // B: 64x16, 16B each
    const int bn = (brow >> 4) * HID + j0 + (brow & 15); // W_hh row: gate*1024 + j

    for (int k0 = 0; k0 < HID; k0 += 16) {
        *(uint2*)(As_hi + arow*24 + acol) = *(const uint2*)(hc_hi + arow*HID + k0 + acol);
        *(uint2*)(As_lo + arow*24 + acol) = *(const uint2*)(hc_lo + arow*HID + k0 + acol);
        *(int4*)(Bs_hi + brow*24 + bcol) = *(const int4*)(g_Whh_hi + (size_t)bn*HID + k0 + bcol);
        *(int4*)(Bs_lo + brow*24 + bcol) = *(const int4*)(g_Whh_lo + (size_t)bn*HID + k0 + bcol);
        __syncthreads();

        wmma::fragment<wmma::matrix_a, 16, 16, 16, __half, wmma::row_major> a_hi[2], a_lo[2];
        wmma::fragment<wmma::matrix_b, 16, 16, 16, __half, wmma::col_major> b_hi, b_lo;
        #pragma unroll
        for (int i = 0; i < 2; i++) {
            wmma::load_matrix_sync(a_hi[i], As_hi + i*16*24, 24);
            wmma::load_matrix_sync(a_lo[i], As_lo + i*16*24, 24);
        }
        wmma::load_matrix_sync(b_hi, Bs_hi + warp*16*24, 24);
        wmma::load_matrix_sync(b_lo, Bs_lo + warp*16*24, 24);
        #pragma unroll
        for (int i = 0; i < 2; i++) {
            wmma::mma_sync(acc[i], a_hi[i], b_hi, acc[i]);
            wmma::mma_sync(acc[i], a_hi[i], b_lo, acc[i]);
            wmma::mma_sync(acc[i], a_lo[i], b_hi, acc[i]);
        }
        __syncthreads();
    }

    #pragma unroll
    for (int i = 0; i < 2; i++)
        wmma::store_matrix_sync(gsm + i*16*68 + warp*16, acc[i], 68, wmma::mem_row_major);
    __syncthreads();

    // Fused LSTM cell update: 512 outputs (32 batch x 16 j), 4 per thread
    for (int idx = tid; idx < 512; idx += 128) {
        const int b = idx >> 4, jj = idx & 15;
        const int j = j0 + jj;
        const size_t xb = (size_t)(b*SEQ + s)*GATES + j;
        float iv = gsm[b*68 + 0*16 + jj] + g_xg[xb]          + b_ih[j]          + b_hh[j];
        float fv = gsm[b*68 + 1*16 + jj] + g_xg[xb + 1024]   + b_ih[1024 + j]   + b_hh[1024 + j];
        float gv = gsm[b*68 + 2*16 + jj] + g_xg[xb + 2048]   + b_ih[2048 + j]   + b_hh[2048 + j];
        float ov = gsm[b*68 + 3*16 + jj] + g_xg[xb + 3072]   + b_ih[3072 + j]   + b_hh[3072 + j];

        float ig = 1.0f / (1.0f + expf(-iv));
        float fg = 1.0f / (1.0f + expf(-fv));
        float gg = tanhf(gv);
        float og = 1.0f / (1.0f + expf(-ov));

        const int ci = b*HID + j;
        float c = fg * g_c[ci] + ig * gg;
        g_c[ci] = c;
        float h = og * tanhf(c);

        __half hh = __float2half_rn(h);
        __half hl = __float2half_rn(h - __half2float(hh));
        const int hs = (b*SEQ + s)*HID + j;
        g_hs_hi[hs] = hh;  g_hs_lo[hs] = hl;
        hn_hi[ci] = hh;    hn_lo[ci] = hl;
    }
}

// ---------------------------------------------------------------------------
// Kernel 3: logits[m, v] = hs[m] @ W_fc^T + b_fc   (M=16384, N=5056pad, K=1024)
// ---------------------------------------------------------------------------
__global__ __launch_bounds__(128) void fc_gemm(const float* __restrict__ b_fc,
                                               float* __restrict__ out) {
    __shared__ __align__(32) __half As_hi[64*24], As_lo[64*24];
    __shared__ __align__(32) __half Bs_hi[64*24], Bs_lo[64*24];
    __shared__ __align__(32) float  Cs[64*68];

    const int n0 = blockIdx.x * 64;
    const int m0 = blockIdx.y * 64;
    const int tid = threadIdx.x;
    const int warp = tid >> 5;
    const int wm = warp >> 1, wn = warp & 1;

    wmma::fragment<wmma::accumulator, 16, 16, 16, float> acc[2][2];
    #pragma unroll
    for (int i = 0; i < 2; i++)
        #pragma unroll
        for (int j = 0; j < 2; j++)
            wmma::fill_fragment(acc[i][j], 0.0f);

    const int lrow = tid >> 1;
    const int lcol = (tid & 1) * 8;
    const int m = m0 + lrow;
    const int n = n0 + lrow;

    for (int k0 = 0; k0 < HID; k0 += 16) {
        *(int4*)(As_hi + lrow*24 + lcol) = *(const int4*)(g_hs_hi + (size_t)m*HID + k0 + lcol);
        *(int4*)(As_lo + lrow*24 + lcol) = *(const int4*)(g_hs_lo + (size_t)m*HID + k0 + lcol);
        *(int4*)(Bs_hi + lrow*24 + lcol) = *(const int4*)(g_Wfc_hi + (size_t)n*HID + k0 + lcol);
        *(int4*)(Bs_lo + lrow*24 + lcol) = *(const int4*)(g_Wfc_lo + (size_t)n*HID + k0 + lcol);
        __syncthreads();

        wmma::fragment<wmma::matrix_a, 16, 16, 16, __half, wmma::row_major> a_hi[2], a_lo[2];
        wmma::fragment<wmma::matrix_b, 16, 16, 16, __half, wmma::col_major> b_hi[2], b_lo[2];
        #pragma unroll
        for (int i = 0; i < 2; i++) {
            wmma::load_matrix_sync(a_hi[i], As_hi + (wm*32 + i*16)*24, 24);
            wmma::load_matrix_sync(a_lo[i], As_lo + (wm*32 + i*16)*24, 24);
        }
        #pragma unroll
        for (int j = 0; j < 2; j++) {
            wmma::load_matrix_sync(b_hi[j], Bs_hi + (wn*32 + j*16)*24, 24);
            wmma::load_matrix_sync(b_lo[j], Bs_lo + (wn*32 + j*16)*24, 24);
        }
        #pragma unroll
        for (int i = 0; i < 2; i++)
            #pragma unroll
            for (int j = 0; j < 2; j++) {
                wmma::mma_sync(acc[i][j], a_hi[i], b_hi[j], acc[i][j]);
                wmma::mma_sync(acc[i][j], a_hi[i], b_lo[j], acc[i][j]);
                wmma::mma_sync(acc[i][j], a_lo[i], b_hi[j], acc[i][j]);
            }
        __syncthreads();
    }

    #pragma unroll
    for (int i = 0; i < 2; i++)
        #pragma unroll
        for (int j = 0; j < 2; j++)
            wmma::store_matrix_sync(Cs + (wm*32 + i*16)*68 + wn*32 + j*16,
                                    acc[i][j], 68, wmma::mem_row_major);
    __syncthreads();

    for (int idx = tid; idx < 64*64; idx += 128) {
        const int rr = idx >> 6, cc = idx & 63;
        const int v = n0 + cc;
        if (v < VOCAB)
            out[(size_t)(m0 + rr)*VOCAB + v] = Cs[rr*68 + cc] + b_fc[v];
    }
}

// ---------------------------------------------------------------------------
// Launch
// ---------------------------------------------------------------------------
extern "C" void kernel_launch(void* const* d_in, const int* in_sizes, int n_in,
                              void* d_out, int out_size) {
    const int*   x    = (const int*)  d_in[0];
    const float* emb  = (const float*)d_in[1];
    const float* W_ih = (const float*)d_in[2];
    const float* W_hh = (const float*)d_in[3];
    const float* b_ih = (const float*)d_in[4];
    const float* b_hh = (const float*)d_in[5];
    const float* W_fc = (const float*)d_in[6];
    const float* b_fc = (const float*)d_in[7];
    float* out = (float*)d_out;

    (void)in_sizes; (void)n_in; (void)out_size;
    (void)W_ih; (void)W_hh; (void)emb; (void)W_fc;

    // Prep: fp32 -> fp16 hi/lo splits (idempotent, runs every call)
    prep_emb<<<512, 256>>>(emb);
    prep_wih<<<512, 256>>>(W_ih);
    prep_whh<<<512, 256>>>(W_hh);
    prep_wfc<<<512, 256>>>(W_fc);
    init_state<<<(BATCH*HID + 255)/256, 256>>>();

    // Input-side GEMM over all timesteps
    embed_gemm<<<dim3(GATES/64, MROWS/64), 128>>>(x);

    // Sequential recurrence: one kernel per timestep
    for (int s = 0; s < SEQ; s++)
        lstm_step<<<HID/16, 128>>>(s, b_ih, b_hh);

    // Vocab projection
    fc_gemm<<<dim3(VPAD/64, MROWS/64), 128>>>(b_fc, out);
}

// round 3
// speedup vs baseline: 3.1196x; 3.1196x over previous
#include <cuda_runtime.h>
#include <cuda_fp16.h>
#include <mma.h>
#include <math.h>

using namespace nvcuda;

#define VOCAB 5000
#define EMB   512
#define HID   1024
#define GATES 4096
#define BATCH 32
#define SEQ   512
#define MROWS (BATCH*SEQ)   /* 16384 */
#define VPAD  5056          /* 79 * 64 */

#define JPC   8             /* j-columns per CTA in recurrence */
#define NCTA  (HID/JPC)     /* 128 persistent CTAs */
#define RPC   (4*JPC)       /* W_hh rows per CTA (4 gates x 8) = 32 */

// ---------------------------------------------------------------------------
// Static device scratch
// ---------------------------------------------------------------------------
__device__ __half g_emb_hi[VOCAB*EMB];
__device__ __half g_emb_lo[VOCAB*EMB];
__device__ __half g_Wih_hi[GATES*EMB];
__device__ __half g_Wih_lo[GATES*EMB];
__device__ __half g_Whh_hi[GATES*HID];
__device__ __half g_Whh_lo[GATES*HID];
__device__ __half g_Wfc_hi[VPAD*HID];
__device__ __half g_Wfc_lo[VPAD*HID];
__device__ float  g_xg[(size_t)MROWS*GATES];     // precomputed x@W_ih^T
__device__ __half g_hs_hi[MROWS*HID];            // all h_t (hi), input to fc
__device__ __half g_h_hi[2][BATCH*HID];          // double-buffered h
__device__ __half g_h_lo[2][BATCH*HID];

// grid barrier state (zero-initialized at module load; gen is monotonic)
__device__ unsigned g_bar_cnt;
__device__ volatile unsigned g_bar_gen;

// ---------------------------------------------------------------------------
// Prep: split fp32 weights into fp16 hi/lo pairs
// ---------------------------------------------------------------------------
__device__ __forceinline__ void split1(float f, __half* hi, __half* lo, int i) {
    __half h = __float2half_rn(f);
    hi[i] = h;
    lo[i] = __float2half_rn(f - __half2float(h));
}

__global__ void prep_emb(const float* __restrict__ src) {
    for (int i = blockIdx.x*blockDim.x + threadIdx.x; i < VOCAB*EMB; i += gridDim.x*blockDim.x)
        split1(src[i], g_emb_hi, g_emb_lo, i);
}
__global__ void prep_wih(const float* __restrict__ src) {
    for (int i = blockIdx.x*blockDim.x + threadIdx.x; i < GATES*EMB; i += gridDim.x*blockDim.x)
        split1(src[i], g_Wih_hi, g_Wih_lo, i);
}
__global__ void prep_whh(const float* __restrict__ src) {
    for (int i = blockIdx.x*blockDim.x + threadIdx.x; i < GATES*HID; i += gridDim.x*blockDim.x)
        split1(src[i], g_Whh_hi, g_Whh_lo, i);
}
__global__ void prep_wfc(const float* __restrict__ src) {
    for (int i = blockIdx.x*blockDim.x + threadIdx.x; i < VPAD*HID; i += gridDim.x*blockDim.x) {
        float f = (i < VOCAB*HID) ? src[i] : 0.0f;
        split1(f, g_Wfc_hi, g_Wfc_lo, i);
    }
}
__global__ void init_state() {
    int i = blockIdx.x*blockDim.x + threadIdx.x;
    if (i < BATCH*HID) {
        g_h_hi[0][i] = __float2half_rn(0.0f);
        g_h_lo[0][i] = __float2half_rn(0.0f);
    }
}

// ---------------------------------------------------------------------------
// Kernel 1: xg = emb[x] @ W_ih^T   (M=16384, N=4096, K=512), 3-pass hi/lo.
// 128x64 CTA tile, 256 threads, 8 warps (4x2), each warp 32x32.
// ---------------------------------------------------------------------------
__global__ __launch_bounds__(256) void embed_gemm(const int* __restrict__ x) {
    __shared__ __align__(16) __half As_hi[128*24], As_lo[128*24];
    __shared__ __align__(16) __half Bs_hi[64*24],  Bs_lo[64*24];
    __shared__ int rowidx[128];

    const int n0 = blockIdx.x * 64;
    const int m0 = blockIdx.y * 128;
    const int tid = threadIdx.x;
    const int warp = tid >> 5;
    const int wm = warp >> 1, wn = warp & 1;

    if (tid < 128) rowidx[tid] = x[m0 + tid];
    __syncthreads();

    wmma::fragment<wmma::accumulator, 16, 16, 16, float> acc[2][2];
    #pragma unroll
    for (int i = 0; i < 2; i++)
        #pragma unroll
        for (int j = 0; j < 2; j++)
            wmma::fill_fragment(acc[i][j], 0.0f);

    const int ar = tid >> 1, ac = (tid & 1) * 8;       // A: 128 rows x 2 int4
    const int bt = tid & 127;
    const int br = bt >> 1, bc = (bt & 1) * 8;         // B: 64 rows x 2 int4
    const __half* __restrict__ Bsrc = (tid < 128) ? g_Wih_hi : g_Wih_lo;
    __half* __restrict__ Bdst = (tid < 128) ? Bs_hi : Bs_lo;

    for (int k0 = 0; k0 < EMB; k0 += 16) {
        const int r = rowidx[ar];
        *(int4*)(As_hi + ar*24 + ac) = *(const int4*)(g_emb_hi + (size_t)r*EMB + k0 + ac);
        *(int4*)(As_lo + ar*24 + ac) = *(const int4*)(g_emb_lo + (size_t)r*EMB + k0 + ac);
        *(int4*)(Bdst + br*24 + bc) = *(const int4*)(Bsrc + (size_t)(n0 + br)*EMB + k0 + bc);
        __syncthreads();

        wmma::fragment<wmma::matrix_a, 16, 16, 16, __half, wmma::row_major> a_hi[2], a_lo[2];
        wmma::fragment<wmma::matrix_b, 16, 16, 16, __half, wmma::col_major> b_hi[2], b_lo[2];
        #pragma unroll
        for (int i = 0; i < 2; i++) {
            wmma::load_matrix_sync(a_hi[i], As_hi + (wm*32 + i*16)*24, 24);
            wmma::load_matrix_sync(a_lo[i], As_lo + (wm*32 + i*16)*24, 24);
        }
        #pragma unroll
        for (int j = 0; j < 2; j++) {
            wmma::load_matrix_sync(b_hi[j], Bs_hi + (wn*32 + j*16)*24, 24);
            wmma::load_matrix_sync(b_lo[j], Bs_lo + (wn*32 + j*16)*24, 24);
        }
        #pragma unroll
        for (int i = 0; i < 2; i++)
            #pragma unroll
            for (int j = 0; j < 2; j++) {
                wmma::mma_sync(acc[i][j], a_hi[i], b_hi[j], acc[i][j]);
                wmma::mma_sync(acc[i][j], a_hi[i], b_lo[j], acc[i][j]);
                wmma::mma_sync(acc[i][j], a_lo[i], b_hi[j], acc[i][j]);
            }
        __syncthreads();
    }

    #pragma unroll
    for (int i = 0; i < 2; i++)
        #pragma unroll
        for (int j = 0; j < 2; j++)
            wmma::store_matrix_sync(
                g_xg + (size_t)(m0 + wm*32 + i*16)*GATES + n0 + wn*32 + j*16,
                acc[i][j], GATES, wmma::mem_row_major);
}

// ---------------------------------------------------------------------------
// Grid barrier (all NCTA CTAs co-resident: 1 CTA/SM by smem, 128 <= 148 SMs)
// ---------------------------------------------------------------------------
__device__ __forceinline__ void grid_barrier() {
    __syncthreads();
    if (threadIdx.x == 0) {
        unsigned my = g_bar_gen;
        __threadfence();
        if (atomicAdd(&g_bar_cnt, 1u) == NCTA - 1u) {
            g_bar_cnt = 0u;
            __threadfence();
            g_bar_gen = my + 1u;
        } else {
            while (g_bar_gen == my) __nanosleep(64);
            __threadfence();
        }
    }
    __syncthreads();
}

// ---------------------------------------------------------------------------
// Kernel 2: persistent LSTM recurrence. 128 CTAs x 128 threads.
// CTA owns j-slice [j0, j0+8); caches its 32 W_hh rows (hi+lo) in smem.
// Per step: gates[32x32] = h[32x1024] @ Wslice^T (3-pass hi/lo), fused cell
// update, h double-buffered in global; c lives in smem for all 512 steps.
// ---------------------------------------------------------------------------
#define SMEM_PERSIST (RPC*1032*2*2 /*W hi+lo*/ + 2*2*32*136*2 /*h stage*/ \
                      + (32*36 + 32*JPC + RPC)*4 /*gates + c + bias*/)

__global__ __launch_bounds__(128, 1) void lstm_persist(const float* __restrict__ b_ih,
                                                       const float* __restrict__ b_hh) {
    extern __shared__ __align__(16) char smraw[];
    __half* sWhi = (__half*)smraw;               // [32][1032]
    __half* sWlo = sWhi + RPC*1032;              // [32][1032]
    __half* sH   = sWlo + RPC*1032;              // [buf2][hl2][32][136]
    float*  gsm  = (float*)(sH + 2*2*32*136);    // [32][36]
    float*  cst  = gsm + 32*36;                  // [32][8]
    float*  bias = cst + 32*JPC;                 // [32]

    const int tid  = threadIdx.x;
    const int warp = tid >> 5;
    const int wm = warp >> 1, wn = warp & 1;     // 4 warps: 2x2 of 16x16
    const int j0 = blockIdx.x * JPC;

    // Cache W_hh slice (hi+lo) in smem once
    for (int i = tid; i < RPC*128; i += 128) {   // 128 int4 per row
        int r = i >> 7, ci = i & 127;
        int gr = (r >> 3)*HID + j0 + (r & 7);
        ((int4*)(sWhi + r*1032))[ci] = ((const int4*)(g_Whh_hi + (size_t)gr*HID))[ci];
        ((int4*)(sWlo + r*1032))[ci] = ((const int4*)(g_Whh_lo + (size_t)gr*HID))[ci];
    }
    if (tid < RPC) {
        int gr = (tid >> 3)*HID + j0 + (tid & 7);
        bias[tid] = b_ih[gr] + b_hh[gr];
    }
    for (int i = tid; i < BATCH*JPC; i += 128) cst[i] = 0.0f;
    __syncthreads();

    const int pb = tid >> 2, pq = tid & 3;       // h-chunk loader mapping

    for (int s = 0; s < SEQ; s++) {
        const __half* __restrict__ hc_hi = g_h_hi[s & 1];
        const __half* __restrict__ hc_lo = g_h_lo[s & 1];
        __half* __restrict__ hn_hi = g_h_hi[(s & 1) ^ 1];
        __half* __restrict__ hn_lo = g_h_lo[(s & 1) ^ 1];

        // prefetch xg contributions for this thread's two cell updates
        float xv[2][4];
        #pragma unroll
        for (int u = 0; u < 2; u++) {
            const int b = (tid >> 3) + u*16;
            const float* xr = g_xg + (size_t)(b*SEQ + s)*GATES + j0 + (tid & 7);
            #pragma unroll
            for (int g = 0; g < 4; g++) xv[u][g] = __ldg(xr + g*HID);
        }

        wmma::fragment<wmma::accumulator, 16, 16, 16, float> accA, accB;
        wmma::fill_fragment(accA, 0.0f);
        wmma::fill_fragment(accB, 0.0f);

        // prefetch h chunk 0 (CK=128: per thread 4 int4 hi + 4 int4 lo)
        int4 pf[8];
        {
            const int4* hi4 = (const int4*)(hc_hi + pb*HID);
            const int4* lo4 = (const int4*)(hc_lo + pb*HID);
            #pragma unroll
            for (int i = 0; i < 4; i++) { pf[i] = hi4[pq + 4*i]; pf[4+i] = lo4[pq + 4*i]; }
        }

        for (int ck = 0; ck < 8; ck++) {
            const int buf = ck & 1;
            __syncthreads();
            {
                int4* dhi = (int4*)(sH + ((buf*2 + 0)*32 + pb)*136);
                int4* dlo = (int4*)(sH + ((buf*2 + 1)*32 + pb)*136);
                #pragma unroll
                for (int i = 0; i < 4; i++) { dhi[pq + 4*i] = pf[i]; dlo[pq + 4*i] = pf[4+i]; }
            }
            __syncthreads();
            if (ck < 7) {   // prefetch next chunk, overlaps with MMA below
                const int4* hi4 = (const int4*)(hc_hi + pb*HID + (ck + 1)*128);
                const int4* lo4 = (const int4*)(hc_lo + pb*HID + (ck + 1)*128);
                #pragma unroll
                for (int i = 0; i < 4; i++) { pf[i] = hi4[pq + 4*i]; pf[4+i] = lo4[pq + 4*i]; }
            }
            #pragma unroll
            for (int ki = 0; ki < 8; ki++) {
                const int kg = ck*128 + ki*16;
                wmma::fragment<wmma::matrix_a, 16, 16, 16, __half, wmma::row_major> a_hi, a_lo;
                wmma::fragment<wmma::matrix_b, 16, 16, 16, __half, wmma::col_major> b_hi, b_lo;
                wmma::load_matrix_sync(a_hi, sH + ((buf*2 + 0)*32 + wm*16)*136 + ki*16, 136);
                wmma::load_matrix_sync(a_lo, sH + ((buf*2 + 1)*32 + wm*16)*136 + ki*16, 136);
                wmma::load_matrix_sync(b_hi, sWhi + (wn*16)*1032 + kg, 1032);
                wmma::load_matrix_sync(b_lo, sWlo + (wn*16)*1032 + kg, 1032);
                wmma::mma_sync(accA, a_hi, b_hi, accA);   // two independent chains
                wmma::mma_sync(accB, a_hi, b_lo, accB);
                wmma::mma_sync(accB, a_lo, b_hi, accB);
            }
        }
        #pragma unroll
        for (int i = 0; i < accA.num_elements; i++) accA.x[i] += accB.x[i];

        wmma::store_matrix_sync(gsm + (wm*16)*36 + wn*16, accA, 36, wmma::mem_row_major);
        __syncthreads();

        // fused cell update: 256 outputs (32 batch x 8 j), 2 per thread
        #pragma unroll
        for (int u = 0; u < 2; u++) {
            const int b  = (tid >> 3) + u*16;
            const int jj = tid & 7;
            const int j  = j0 + jj;
            float iv = gsm[b*36 +  0 + jj] + xv[u][0] + bias[ 0 + jj];
            float fv = gsm[b*36 +  8 + jj] + xv[u][1] + bias[ 8 + jj];
            float gv = gsm[b*36 + 16 + jj] + xv[u][2] + bias[16 + jj];
            float ov = gsm[b*36 + 24 + jj] + xv[u][3] + bias[24 + jj];

            float ig = 1.0f / (1.0f + expf(-iv));
            float fg = 1.0f / (1.0f + expf(-fv));
            float gg = tanhf(gv);
            float og = 1.0f / (1.0f + expf(-ov));

            float c = fg * cst[b*JPC + jj] + ig * gg;
            cst[b*JPC + jj] = c;
            float h = og * tanhf(c);

            __half hh = __float2half_rn(h);
            __half hl = __float2half_rn(h - __half2float(hh));
            hn_hi[b*HID + j] = hh;
            hn_lo[b*HID + j] = hl;
            g_hs_hi[(size_t)(b*SEQ + s)*HID + j] = hh;
        }
        grid_barrier();
    }
}

// ---------------------------------------------------------------------------
// Kernel 3: logits = hs @ W_fc^T + b_fc  (M=16384, N=5056pad, K=1024)
// 128x64 tile, 256 threads, 2-pass (a_hi*b_hi + a_hi*b_lo).
// ---------------------------------------------------------------------------
__global__ __launch_bounds__(256) void fc_gemm(const float* __restrict__ b_fc,
                                               float* __restrict__ out) {
    __shared__ __align__(16) __half As_hi[128*24];
    __shared__ __align__(16) __half Bs_hi[64*24], Bs_lo[64*24];
    __shared__ __align__(16) float  Cs[128*68];

    const int n0 = blockIdx.x * 64;
    const int m0 = blockIdx.y * 128;
    const int tid = threadIdx.x;
    const int warp = tid >> 5;
    const int wm = warp >> 1, wn = warp & 1;

    wmma::fragment<wmma::accumulator, 16, 16, 16, float> acc[2][2];
    #pragma unroll
    for (int i = 0; i < 2; i++)
        #pragma unroll
        for (int j = 0; j < 2; j++)
            wmma::fill_fragment(acc[i][j], 0.0f);

    const int ar = tid >> 1, ac = (tid & 1) * 8;
    const int bt = tid & 127;
    const int br = bt >> 1, bc = (bt & 1) * 8;
    const __half* __restrict__ Bsrc = (tid < 128) ? g_Wfc_hi : g_Wfc_lo;
    __half* __restrict__ Bdst = (tid < 128) ? Bs_hi : Bs_lo;

    for (int k0 = 0; k0 < HID; k0 += 16) {
        *(int4*)(As_hi + ar*24 + ac) = *(const int4*)(g_hs_hi + (size_t)(m0 + ar)*HID + k0 + ac);
        *(int4*)(Bdst + br*24 + bc) = *(const int4*)(Bsrc + (size_t)(n0 + br)*HID + k0 + bc);
        __syncthreads();

        wmma::fragment<wmma::matrix_a, 16, 16, 16, __half, wmma::row_major> a_hi[2];
        wmma::fragment<wmma::matrix_b, 16, 16, 16, __half, wmma::col_major> b_hi[2], b_lo[2];
        #pragma unroll
        for (int i = 0; i < 2; i++)
            wmma::load_matrix_sync(a_hi[i], As_hi + (wm*32 + i*16)*24, 24);
        #pragma unroll
        for (int j = 0; j < 2; j++) {
            wmma::load_matrix_sync(b_hi[j], Bs_hi + (wn*32 + j*16)*24, 24);
            wmma::load_matrix_sync(b_lo[j], Bs_lo + (wn*32 + j*16)*24, 24);
        }
        #pragma unroll
        for (int i = 0; i < 2; i++)
            #pragma unroll
            for (int j = 0; j < 2; j++) {
                wmma::mma_sync(acc[i][j], a_hi[i], b_hi[j], acc[i][j]);
                wmma::mma_sync(acc[i][j], a_hi[i], b_lo[j], acc[i][j]);
            }
        __syncthreads();
    }

    #pragma unroll
    for (int i = 0; i < 2; i++)
        #pragma unroll
        for (int j = 0; j < 2; j++)
            wmma::store_matrix_sync(Cs + (wm*32 + i*16)*68 + wn*32 + j*16,
                                    acc[i][j], 68, wmma::mem_row_major);
    __syncthreads();

    for (int idx = tid; idx < 128*64; idx += 256) {
        const int rr = idx >> 6, cc = idx & 63;
        const int v = n0 + cc;
        if (v < VOCAB)
            out[(size_t)(m0 + rr)*VOCAB + v] = Cs[rr*68 + cc] + b_fc[v];
    }
}

// ---------------------------------------------------------------------------
// Launch
// ---------------------------------------------------------------------------
extern "C" void kernel_launch(void* const* d_in, const int* in_sizes, int n_in,
                              void* d_out, int out_size) {
    const int*   x    = (const int*)  d_in[0];
    const float* emb  = (const float*)d_in[1];
    const float* W_ih = (const float*)d_in[2];
    const float* W_hh = (const float*)d_in[3];
    const float* b_ih = (const float*)d_in[4];
    const float* b_hh = (const float*)d_in[5];
    const float* W_fc = (const float*)d_in[6];
    const float* b_fc = (const float*)d_in[7];
    float* out = (float*)d_out;

    (void)in_sizes; (void)n_in; (void)out_size;

    prep_emb<<<512, 256>>>(emb);
    prep_wih<<<512, 256>>>(W_ih);
    prep_whh<<<512, 256>>>(W_hh);
    prep_wfc<<<512, 256>>>(W_fc);
    init_state<<<(BATCH*HID + 255)/256, 256>>>();

    embed_gemm<<<dim3(GATES/64, MROWS/128), 256>>>(x);

    cudaFuncSetAttribute(lstm_persist, cudaFuncAttributeMaxDynamicSharedMemorySize,
                         SMEM_PERSIST);
    lstm_persist<<<NCTA, 128, SMEM_PERSIST>>>(b_ih, b_hh);

    fc_gemm<<<dim3(VPAD/64, MROWS/128), 256>>>(b_fc, out);
}

// round 5
// speedup vs baseline: 3.2365x; 1.0375x over previous
#include <cuda_runtime.h>
#include <cuda_fp16.h>
#include <mma.h>
#include <math.h>

using namespace nvcuda;

#define VOCAB 5000
#define EMB   512
#define HID   1024
#define GATES 4096
#define BATCH 32
#define SEQ   512
#define MROWS (BATCH*SEQ)   /* 16384 */
#define VPAD  5120          /* 40 * 128 */

#define JPC   8             /* j-columns per CTA in recurrence */
#define NCTA  (HID/JPC)     /* 128 persistent CTAs */
#define RPC   (4*JPC)       /* W_hh rows per CTA = 32 */

// ---------------------------------------------------------------------------
// Static device scratch
// ---------------------------------------------------------------------------
__device__ __half g_emb_hi[VOCAB*EMB];
__device__ __half g_emb_lo[VOCAB*EMB];
__device__ __half g_Wih_hi[GATES*EMB];
__device__ __half g_Wih_lo[GATES*EMB];
__device__ __half g_Whh_hi[GATES*HID];
__device__ __half g_Whh_lo[GATES*HID];
__device__ __half g_Wfc_hi[(size_t)VPAD*HID];
__device__ __half g_Wfc_lo[(size_t)VPAD*HID];
__device__ float  g_xg[(size_t)MROWS*GATES];
__device__ __half g_hs_hi[MROWS*HID];
__device__ __half g_h_hi[2][BATCH*HID];
__device__ __half g_h_lo[2][BATCH*HID];

__device__ unsigned g_bar_cnt;
__device__ volatile unsigned g_bar_gen;

// ---------------------------------------------------------------------------
// Prep
// ---------------------------------------------------------------------------
__device__ __forceinline__ void split1(float f, __half* hi, __half* lo, size_t i) {
    __half h = __float2half_rn(f);
    hi[i] = h;
    lo[i] = __float2half_rn(f - __half2float(h));
}

__global__ void prep_emb(const float* __restrict__ src) {
    for (int i = blockIdx.x*blockDim.x + threadIdx.x; i < VOCAB*EMB; i += gridDim.x*blockDim.x)
        split1(src[i], g_emb_hi, g_emb_lo, i);
}
__global__ void prep_wih(const float* __restrict__ src) {
    for (int i = blockIdx.x*blockDim.x + threadIdx.x; i < GATES*EMB; i += gridDim.x*blockDim.x)
        split1(src[i], g_Wih_hi, g_Wih_lo, i);
}
__global__ void prep_whh(const float* __restrict__ src) {
    for (int i = blockIdx.x*blockDim.x + threadIdx.x; i < GATES*HID; i += gridDim.x*blockDim.x)
        split1(src[i], g_Whh_hi, g_Whh_lo, i);
}
__global__ void prep_wfc(const float* __restrict__ src) {
    for (size_t i = blockIdx.x*blockDim.x + threadIdx.x; i < (size_t)VPAD*HID; i += (size_t)gridDim.x*blockDim.x) {
        float f = (i < (size_t)VOCAB*HID) ? src[i] : 0.0f;
        split1(f, g_Wfc_hi, g_Wfc_lo, i);
    }
}
__global__ void init_state() {
    int i = blockIdx.x*blockDim.x + threadIdx.x;
    if (i < BATCH*HID) {
        g_h_hi[0][i] = __float2half_rn(0.0f);
        g_h_lo[0][i] = __float2half_rn(0.0f);
    }
}

// ---------------------------------------------------------------------------
// Kernel 1: xg = emb[x] @ W_ih^T  (M=16384, N=4096, K=512), 3-pass hi/lo.
// 128x128 CTA tile, 256 threads (8 warps as 4x2), warp = 32x64 out.
// KC=32 per stage.
// ---------------------------------------------------------------------------
__global__ __launch_bounds__(256) void embed_gemm(const int* __restrict__ x) {
    __shared__ __align__(16) __half As_hi[128*40], As_lo[128*40];
    __shared__ __align__(16) __half Bs_hi[128*40], Bs_lo[128*40];
    __shared__ int rowidx[128];

    const int n0 = blockIdx.x * 128;
    const int m0 = blockIdx.y * 128;
    const int tid = threadIdx.x;
    const int warp = tid >> 5;
    const int wm = warp >> 1, wn = warp & 1;

    if (tid < 128) rowidx[tid] = x[m0 + tid];
    __syncthreads();

    wmma::fragment<wmma::accumulator, 16, 16, 16, float> acc[2][4];
    #pragma unroll
    for (int i = 0; i < 2; i++)
        #pragma unroll
        for (int j = 0; j < 4; j++)
            wmma::fill_fragment(acc[i][j], 0.0f);

    for (int k0 = 0; k0 < EMB; k0 += 32) {
        #pragma unroll
        for (int it = 0; it < 2; it++) {
            const int idx = tid + it*256;        // 512 int4 slots per matrix
            const int row = idx >> 2, c4 = idx & 3;
            const int r = rowidx[row];
            *(int4*)(As_hi + row*40 + c4*8) = *(const int4*)(g_emb_hi + (size_t)r*EMB + k0 + c4*8);
            *(int4*)(As_lo + row*40 + c4*8) = *(const int4*)(g_emb_lo + (size_t)r*EMB + k0 + c4*8);
            const int n = n0 + row;
            *(int4*)(Bs_hi + row*40 + c4*8) = *(const int4*)(g_Wih_hi + (size_t)n*EMB + k0 + c4*8);
            *(int4*)(Bs_lo + row*40 + c4*8) = *(const int4*)(g_Wih_lo + (size_t)n*EMB + k0 + c4*8);
        }
        __syncthreads();

        #pragma unroll
        for (int ks = 0; ks < 2; ks++) {
            wmma::fragment<wmma::matrix_a, 16, 16, 16, __half, wmma::row_major> a_hi[2], a_lo[2];
            wmma::fragment<wmma::matrix_b, 16, 16, 16, __half, wmma::col_major> b_hi[4], b_lo[4];
            #pragma unroll
            for (int i = 0; i < 2; i++) {
                wmma::load_matrix_sync(a_hi[i], As_hi + (wm*32 + i*16)*40 + ks*16, 40);
                wmma::load_matrix_sync(a_lo[i], As_lo + (wm*32 + i*16)*40 + ks*16, 40);
            }
            #pragma unroll
            for (int j = 0; j < 4; j++) {
                wmma::load_matrix_sync(b_hi[j], Bs_hi + (wn*64 + j*16)*40 + ks*16, 40);
                wmma::load_matrix_sync(b_lo[j], Bs_lo + (wn*64 + j*16)*40 + ks*16, 40);
            }
            #pragma unroll
            for (int i = 0; i < 2; i++)
                #pragma unroll
                for (int j = 0; j < 4; j++) {
                    wmma::mma_sync(acc[i][j], a_hi[i], b_hi[j], acc[i][j]);
                    wmma::mma_sync(acc[i][j], a_hi[i], b_lo[j], acc[i][j]);
                    wmma::mma_sync(acc[i][j], a_lo[i], b_hi[j], acc[i][j]);
                }
        }
        __syncthreads();
    }

    #pragma unroll
    for (int i = 0; i < 2; i++)
        #pragma unroll
        for (int j = 0; j < 4; j++)
            wmma::store_matrix_sync(
                g_xg + (size_t)(m0 + wm*32 + i*16)*GATES + n0 + wn*64 + j*16,
                acc[i][j], GATES, wmma::mem_row_major);
}

// ---------------------------------------------------------------------------
// Grid barrier (single-wave persistent kernel)
// ---------------------------------------------------------------------------
__device__ __forceinline__ void grid_barrier() {
    __syncthreads();
    if (threadIdx.x == 0) {
        unsigned my = g_bar_gen;
        __threadfence();
        if (atomicAdd(&g_bar_cnt, 1u) == NCTA - 1u) {
            g_bar_cnt = 0u;
            __threadfence();
            g_bar_gen = my + 1u;
        } else {
            while (g_bar_gen == my) __nanosleep(64);
            __threadfence();
        }
    }
    __syncthreads();
}

// ---------------------------------------------------------------------------
// Kernel 2: persistent LSTM recurrence. 128 CTAs x 256 threads.
// CTA owns j-slice [j0, j0+8); W_hh slice (hi+lo) cached in smem.
// 8 warps in 2 k-groups of 4; group g handles K in [g*512, g*512+512).
// Per group: 4 chunks of 128 k, double-buffered h staging.
// sH layout [g][buf][hl][32][136]: hl stride is 32 rows.  (R3 bug: used
// 64-row stride, colliding grp0/buf1-lo with grp1/buf0-hi -> NaN.)
// ---------------------------------------------------------------------------
#define SM_W    (RPC*1032)                    /* halves per W matrix */
#define SM_H    (2*2*2*32*136)                /* group,buf,hilo,32,136 halves */
#define SMEM_PERSIST ((2*SM_W + SM_H)*2 + (2*32*36 + 32*JPC + RPC)*4)

__global__ __launch_bounds__(256, 1) void lstm_persist(const float* __restrict__ b_ih,
                                                       const float* __restrict__ b_hh) {
    extern __shared__ __align__(16) char smraw[];
    __half* sWhi = (__half*)smraw;               // [32][1032]
    __half* sWlo = sWhi + SM_W;                  // [32][1032]
    __half* sH   = sWlo + SM_W;                  // [g][buf][hl][32][136]
    float*  gsm  = (float*)(sH + SM_H);          // [2][32][36]
    float*  cst  = gsm + 2*32*36;                // [32][8]
    float*  bias = cst + 32*JPC;                 // [32]

    const int tid  = threadIdx.x;
    const int warp = tid >> 5;
    const int grp  = warp >> 2;                  // k-group 0/1
    const int w2   = warp & 3;
    const int wm = w2 >> 1, wn = w2 & 1;
    const int j0 = blockIdx.x * JPC;

    // Cache W_hh slice (hi+lo) once
    for (int i = tid; i < RPC*128; i += 256) {   // 128 int4 per row
        int r = i >> 7, ci = i & 127;
        int gr = (r >> 3)*HID + j0 + (r & 7);
        ((int4*)(sWhi + r*1032))[ci] = ((const int4*)(g_Whh_hi + (size_t)gr*HID))[ci];
        ((int4*)(sWlo + r*1032))[ci] = ((const int4*)(g_Whh_lo + (size_t)gr*HID))[ci];
    }
    if (tid < RPC) {
        int gr = (tid >> 3)*HID + j0 + (tid & 7);
        bias[tid] = b_ih[gr] + b_hh[gr];
    }
    for (int i = tid; i < BATCH*JPC; i += 256) cst[i] = 0.0f;
    __syncthreads();

    const int t4 = tid & 127;
    const int pb = t4 >> 2, pq = t4 & 3;         // loader: 32 rows x 4 int4

    for (int s = 0; s < SEQ; s++) {
        const __half* __restrict__ hc_hi = g_h_hi[s & 1];
        const __half* __restrict__ hc_lo = g_h_lo[s & 1];
        __half* __restrict__ hn_hi = g_h_hi[(s & 1) ^ 1];
        __half* __restrict__ hn_lo = g_h_lo[(s & 1) ^ 1];

        // prefetch xg for this thread's single cell update
        float xv[4];
        {
            const int b = tid >> 3;
            const float* xr = g_xg + (size_t)(b*SEQ + s)*GATES + j0 + (tid & 7);
            #pragma unroll
            for (int g = 0; g < 4; g++) xv[g] = __ldg(xr + g*HID);
        }

        wmma::fragment<wmma::accumulator, 16, 16, 16, float> accA, accB;
        wmma::fill_fragment(accA, 0.0f);
        wmma::fill_fragment(accB, 0.0f);

        // prefetch this group's chunk 0
        int4 pf[8];
        {
            const int4* hi4 = (const int4*)(hc_hi + pb*HID + grp*512);
            const int4* lo4 = (const int4*)(hc_lo + pb*HID + grp*512);
            #pragma unroll
            for (int i = 0; i < 4; i++) { pf[i] = hi4[pq + 4*i]; pf[4+i] = lo4[pq + 4*i]; }
        }

        for (int ck = 0; ck < 4; ck++) {
            const int buf = ck & 1;
            __half* base = sH + (((grp*2 + buf)*2 + 0)*32)*136;   // hl=0 plane
            __syncthreads();
            {
                int4* dhi = (int4*)(base + pb*136);
                int4* dlo = (int4*)(base + (32 + pb)*136);        // hl=1 plane (+32 rows)
                #pragma unroll
                for (int i = 0; i < 4; i++) { dhi[pq + 4*i] = pf[i]; dlo[pq + 4*i] = pf[4+i]; }
            }
            __syncthreads();
            if (ck < 3) {
                const int4* hi4 = (const int4*)(hc_hi + pb*HID + grp*512 + (ck + 1)*128);
                const int4* lo4 = (const int4*)(hc_lo + pb*HID + grp*512 + (ck + 1)*128);
                #pragma unroll
                for (int i = 0; i < 4; i++) { pf[i] = hi4[pq + 4*i]; pf[4+i] = lo4[pq + 4*i]; }
            }
            #pragma unroll
            for (int ki = 0; ki < 8; ki++) {
                const int kg = grp*512 + ck*128 + ki*16;
                wmma::fragment<wmma::matrix_a, 16, 16, 16, __half, wmma::row_major> a_hi, a_lo;
                wmma::fragment<wmma::matrix_b, 16, 16, 16, __half, wmma::col_major> b_hi, b_lo;
                wmma::load_matrix_sync(a_hi, base + (wm*16)*136 + ki*16, 136);
                wmma::load_matrix_sync(a_lo, base + (32 + wm*16)*136 + ki*16, 136);
                wmma::load_matrix_sync(b_hi, sWhi + (wn*16)*1032 + kg, 1032);
                wmma::load_matrix_sync(b_lo, sWlo + (wn*16)*1032 + kg, 1032);
                wmma::mma_sync(accA, a_hi, b_hi, accA);
                wmma::mma_sync(accB, a_hi, b_lo, accB);
                wmma::mma_sync(accB, a_lo, b_hi, accB);
            }
        }
        #pragma unroll
        for (int i = 0; i < accA.num_elements; i++) accA.x[i] += accB.x[i];

        wmma::store_matrix_sync(gsm + grp*32*36 + (wm*16)*36 + wn*16, accA, 36,
                                wmma::mem_row_major);
        __syncthreads();

        // fused cell update: one output per thread (32 batch x 8 j)
        {
            const int b  = tid >> 3;
            const int jj = tid & 7;
            const int j  = j0 + jj;
            float iv = gsm[b*36 +  0 + jj] + gsm[32*36 + b*36 +  0 + jj] + xv[0] + bias[ 0 + jj];
            float fv = gsm[b*36 +  8 + jj] + gsm[32*36 + b*36 +  8 + jj] + xv[1] + bias[ 8 + jj];
            float gv = gsm[b*36 + 16 + jj] + gsm[32*36 + b*36 + 16 + jj] + xv[2] + bias[16 + jj];
            float ov = gsm[b*36 + 24 + jj] + gsm[32*36 + b*36 + 24 + jj] + xv[3] + bias[24 + jj];

            float ig = 1.0f / (1.0f + expf(-iv));
            float fg = 1.0f / (1.0f + expf(-fv));
            float gg = tanhf(gv);
            float og = 1.0f / (1.0f + expf(-ov));

            float c = fg * cst[b*JPC + jj] + ig * gg;
            cst[b*JPC + jj] = c;
            float h = og * tanhf(c);

            __half hh = __float2half_rn(h);
            __half hl = __float2half_rn(h - __half2float(hh));
            hn_hi[b*HID + j] = hh;
            hn_lo[b*HID + j] = hl;
            g_hs_hi[(size_t)(b*SEQ + s)*HID + j] = hh;
        }
        grid_barrier();
    }
}

// ---------------------------------------------------------------------------
// Kernel 3: logits = hs @ W_fc^T + b_fc  (M=16384, N=5120pad, K=1024)
// 128x128 tile, 256 threads, 2-pass (a_hi*b_hi + a_hi*b_lo), KC=32.
// ---------------------------------------------------------------------------
__global__ __launch_bounds__(256) void fc_gemm(const float* __restrict__ b_fc,
                                               float* __restrict__ out) {
    __shared__ __align__(16) __half As_hi[128*40];
    __shared__ __align__(16) __half Bs_hi[128*40], Bs_lo[128*40];
    __shared__ __align__(32) float  Cw[8][16*24];

    const int n0 = blockIdx.x * 128;
    const int m0 = blockIdx.y * 128;
    const int tid = threadIdx.x;
    const int warp = tid >> 5;
    const int lane = tid & 31;
    const int wm = warp >> 1, wn = warp & 1;

    wmma::fragment<wmma::accumulator, 16, 16, 16, float> acc[2][4];
    #pragma unroll
    for (int i = 0; i < 2; i++)
        #pragma unroll
        for (int j = 0; j < 4; j++)
            wmma::fill_fragment(acc[i][j], 0.0f);

    for (int k0 = 0; k0 < HID; k0 += 32) {
        #pragma unroll
        for (int it = 0; it < 2; it++) {
            const int idx = tid + it*256;
            const int row = idx >> 2, c4 = idx & 3;
            *(int4*)(As_hi + row*40 + c4*8) = *(const int4*)(g_hs_hi + (size_t)(m0 + row)*HID + k0 + c4*8);
            const int n = n0 + row;
            *(int4*)(Bs_hi + row*40 + c4*8) = *(const int4*)(g_Wfc_hi + (size_t)n*HID + k0 + c4*8);
            *(int4*)(Bs_lo + row*40 + c4*8) = *(const int4*)(g_Wfc_lo + (size_t)n*HID + k0 + c4*8);
        }
        __syncthreads();

        #pragma unroll
        for (int ks = 0; ks < 2; ks++) {
            wmma::fragment<wmma::matrix_a, 16, 16, 16, __half, wmma::row_major> a_hi[2];
            wmma::fragment<wmma::matrix_b, 16, 16, 16, __half, wmma::col_major> b_hi[4], b_lo[4];
            #pragma unroll
            for (int i = 0; i < 2; i++)
                wmma::load_matrix_sync(a_hi[i], As_hi + (wm*32 + i*16)*40 + ks*16, 40);
            #pragma unroll
            for (int j = 0; j < 4; j++) {
                wmma::load_matrix_sync(b_hi[j], Bs_hi + (wn*64 + j*16)*40 + ks*16, 40);
                wmma::load_matrix_sync(b_lo[j], Bs_lo + (wn*64 + j*16)*40 + ks*16, 40);
            }
            #pragma unroll
            for (int i = 0; i < 2; i++)
                #pragma unroll
                for (int j = 0; j < 4; j++) {
                    wmma::mma_sync(acc[i][j], a_hi[i], b_hi[j], acc[i][j]);
                    wmma::mma_sync(acc[i][j], a_hi[i], b_lo[j], acc[i][j]);
                }
        }
        __syncthreads();
    }

    // epilogue: per-warp staging, add bias, guard VOCAB
    #pragma unroll
    for (int i = 0; i < 2; i++)
        #pragma unroll
        for (int j = 0; j < 4; j++) {
            __syncwarp();
            wmma::store_matrix_sync(Cw[warp], acc[i][j], 24, wmma::mem_row_major);
            __syncwarp();
            const int mbase = m0 + wm*32 + i*16;
            const int nbase = n0 + wn*64 + j*16;
            #pragma unroll
            for (int e = 0; e < 8; e++) {
                const int idx = lane*8 + e;
                const int rr = idx >> 4, cc = idx & 15;
                const int v = nbase + cc;
                if (v < VOCAB)
                    out[(size_t)(mbase + rr)*VOCAB + v] = Cw[warp][rr*24 + cc] + b_fc[v];
            }
        }
}

// ---------------------------------------------------------------------------
// Launch
// ---------------------------------------------------------------------------
extern "C" void kernel_launch(void* const* d_in, const int* in_sizes, int n_in,
                              void* d_out, int out_size) {
    const int*   x    = (const int*)  d_in[0];
    const float* emb  = (const float*)d_in[1];
    const float* W_ih = (const float*)d_in[2];
    const float* W_hh = (const float*)d_in[3];
    const float* b_ih = (const float*)d_in[4];
    const float* b_hh = (const float*)d_in[5];
    const float* W_fc = (const float*)d_in[6];
    const float* b_fc = (const float*)d_in[7];
    float* out = (float*)d_out;

    (void)in_sizes; (void)n_in; (void)out_size;

    prep_emb<<<512, 256>>>(emb);
    prep_wih<<<512, 256>>>(W_ih);
    prep_whh<<<512, 256>>>(W_hh);
    prep_wfc<<<512, 256>>>(W_fc);
    init_state<<<(BATCH*HID + 255)/256, 256>>>();

    embed_gemm<<<dim3(GATES/128, MROWS/128), 256>>>(x);

    cudaFuncSetAttribute(lstm_persist, cudaFuncAttributeMaxDynamicSharedMemorySize,
                         SMEM_PERSIST);
    lstm_persist<<<NCTA, 256, SMEM_PERSIST>>>(b_ih, b_hh);

    fc_gemm<<<dim3(VPAD/128, MROWS/128), 256>>>(b_fc, out);
}